// round 14
// baseline (speedup 1.0000x reference)
#include <cuda_runtime.h>
#include <cuda_fp16.h>
#include <cuda_bf16.h>
#include <mma.h>
#include <cstddef>
#include <cstdint>

using namespace nvcuda;

#define B_   4
#define D_   256
#define E_   512
#define C_   256
#define NEG_INF -1e9f

typedef unsigned long long ull;

// Scratch. h buffers: proj as half for c%8 in {0..3}: row = 128 halves,
// position (c>>3)*4 + (c&3). f buffers: tanh(proj) as f32 for c%8 in {4..7}.
__device__ __half g_enc_h[B_ * E_ * 128];
__device__ float  g_enc_f[B_ * E_ * 128];
__device__ __half g_dec_h[B_ * D_ * 128];
__device__ float  g_dec_f[B_ * D_ * 128];
__device__ float  g_scores[B_ * D_ * E_];

__device__ __forceinline__ __half2 tanh2h(__half2 x) {
    unsigned int r, xi = *reinterpret_cast<unsigned int*>(&x);
    asm("tanh.approx.f16x2 %0, %1;" : "=r"(r) : "r"(xi));
    return *reinterpret_cast<__half2*>(&r);
}
__device__ __forceinline__ __half2 u2h(unsigned int u) {
    return *reinterpret_cast<__half2*>(&u);
}
__device__ __forceinline__ float tanhf_fast(float x) {
    float y; asm("tanh.approx.f32 %0, %1;" : "=f"(y) : "f"(x)); return y;
}
__device__ __forceinline__ ull fma2_(ull a, ull b, ull c) {
    ull d; asm("fma.rn.f32x2 %0, %1, %2, %3;" : "=l"(d) : "l"(a), "l"(b), "l"(c)); return d;
}
__device__ __forceinline__ ull add2_(ull a, ull b) {
    ull d; asm("add.rn.f32x2 %0, %1, %2;" : "=l"(d) : "l"(a), "l"(b)); return d;
}
__device__ __forceinline__ ull mul2_(ull a, ull b) {
    ull d; asm("mul.rn.f32x2 %0, %1, %2;" : "=l"(d) : "l"(a), "l"(b)); return d;
}

#define ONE2_  0x3F8000003F800000ull
#define NTWO2_ 0xC0000000C0000000ull

__device__ __forceinline__ ull tanh_sum_acc1(ull ta, ull tb, ull nv, ull acc) {
    ull num = add2_(ta, tb);
    ull den = fma2_(ta, tb, ONE2_);          // 1 + ta*tb in (0,2]
    ull r0;
    asm("{\n\t.reg .b32 lo, hi;\n\t"
        "mov.b64 {lo, hi}, %1;\n\t"
        "sub.u32 lo, 0x7EF311C3, lo;\n\t"
        "sub.u32 hi, 0x7EF311C3, hi;\n\t"
        "mov.b64 %0, {lo, hi};\n\t}" : "=l"(r0) : "l"(den));
    ull u1  = fma2_(den, r0, NTWO2_);
    ull r1n = mul2_(r0, u1);                 // -1/den
    ull t   = mul2_(num, r1n);               // -tanh(a+b)
    return fma2_(t, nv, acc);
}
__device__ __forceinline__ ull pku(unsigned lo, unsigned hi) {
    return ((ull)hi << 32) | lo;
}

// ---------------------------------------------------------------------------
// wmma GEMM: per CTA 64 rows x 64 W-cols x K=256, bf16 hi/lo split, f32 acc.
// D = Ah*Bh + Ah*Bl + Al*Bh (lo*lo dropped, ~2^-18). 8 warps = 4m x 2n;
// warp = 16 rows x 32 cols (2 accum frags). W[n,k] row-major == matrix_b
// col_major with ldm = pitch.
// grid: x = 4 col tiles, y = 48 row tiles (0..31 enc, 32..47 dec), z = 1.
// Epilogue: C -> smem -> h2 buffer (c%8 0..3) + tanh'd f32 (c%8 4..7).
// ---------------------------------------------------------------------------
#define PXB 272                        // bf16 pitch (row stride), 544 B
#define XH_OFF 0
#define XL_OFF (64 * PXB * 2)
#define WH_OFF (2 * 64 * PXB * 2)
#define WL_OFF (3 * 64 * PXB * 2)
#define GEMM_SMEM (4 * 64 * PXB * 2)   // 139264 B

__global__ __launch_bounds__(256) void gemm_tc_kernel(
        const float* __restrict__ enc, const float* __restrict__ dec,
        const float* __restrict__ W1,  const float* __restrict__ W2) {
    extern __shared__ char smc[];
    __nv_bfloat16* XH = (__nv_bfloat16*)(smc + XH_OFF);
    __nv_bfloat16* XL = (__nv_bfloat16*)(smc + XL_OFF);
    __nv_bfloat16* WH = (__nv_bfloat16*)(smc + WH_OFF);
    __nv_bfloat16* WL = (__nv_bfloat16*)(smc + WL_OFF);

    const int t = threadIdx.x;
    const int col0 = blockIdx.x * 64;
    const int yt = blockIdx.y;
    const bool is_enc = (yt < 32);
    const int b    = is_enc ? (yt >> 3) : ((yt - 32) >> 2);
    const int row0 = is_enc ? (yt & 7) * 64 : ((yt - 32) & 3) * 64;
    const int R    = is_enc ? E_ : D_;
    const float* X = is_enc ? enc : dec;
    const float* W = is_enc ? W1  : W2;
    __half* outh   = is_enc ? g_enc_h : g_dec_h;
    float*  outf   = is_enc ? g_enc_f : g_dec_f;

    // Fill X tile (64 x 256 f32) as bf16 hi/lo
    const float* Xb = X + ((size_t)b * R + row0) * C_;
    for (int i = t; i < 64 * 64; i += 256) {
        int row = i >> 6, c4 = (i & 63) << 2;
        float4 x = *(const float4*)(Xb + row * C_ + c4);
        float fx[4] = {x.x, x.y, x.z, x.w};
        unsigned short hb[4], lb[4];
#pragma unroll
        for (int j = 0; j < 4; j++) {
            __nv_bfloat16 h = __float2bfloat16(fx[j]);
            hb[j] = *reinterpret_cast<unsigned short*>(&h);
            __nv_bfloat16 l = __float2bfloat16(fx[j] - __bfloat162float(h));
            lb[j] = *reinterpret_cast<unsigned short*>(&l);
        }
        *(uint2*)(XH + row * PXB + c4) =
            make_uint2((uint32_t)hb[0] | ((uint32_t)hb[1] << 16),
                       (uint32_t)hb[2] | ((uint32_t)hb[3] << 16));
        *(uint2*)(XL + row * PXB + c4) =
            make_uint2((uint32_t)lb[0] | ((uint32_t)lb[1] << 16),
                       (uint32_t)lb[2] | ((uint32_t)lb[3] << 16));
    }
    // Fill W tile (64 x 256 f32) as bf16 hi/lo
    const float* Wb = W + (size_t)col0 * C_;
    for (int i = t; i < 64 * 64; i += 256) {
        int row = i >> 6, c4 = (i & 63) << 2;
        float4 x = *(const float4*)(Wb + row * C_ + c4);
        float fx[4] = {x.x, x.y, x.z, x.w};
        unsigned short hb[4], lb[4];
#pragma unroll
        for (int j = 0; j < 4; j++) {
            __nv_bfloat16 h = __float2bfloat16(fx[j]);
            hb[j] = *reinterpret_cast<unsigned short*>(&h);
            __nv_bfloat16 l = __float2bfloat16(fx[j] - __bfloat162float(h));
            lb[j] = *reinterpret_cast<unsigned short*>(&l);
        }
        *(uint2*)(WH + row * PXB + c4) =
            make_uint2((uint32_t)hb[0] | ((uint32_t)hb[1] << 16),
                       (uint32_t)hb[2] | ((uint32_t)hb[3] << 16));
        *(uint2*)(WL + row * PXB + c4) =
            make_uint2((uint32_t)lb[0] | ((uint32_t)lb[1] << 16),
                       (uint32_t)lb[2] | ((uint32_t)lb[3] << 16));
    }
    __syncthreads();

    const int w  = t >> 5;
    const int m0 = (w >> 1) * 16;
    const int n0 = (w & 1) * 32;

    wmma::fragment<wmma::matrix_a, 16, 16, 16, __nv_bfloat16, wmma::row_major> ah, al;
    wmma::fragment<wmma::matrix_b, 16, 16, 16, __nv_bfloat16, wmma::col_major> bh0, bh1, bl0, bl1;
    wmma::fragment<wmma::accumulator, 16, 16, 16, float> c0, c1;
    wmma::fill_fragment(c0, 0.f);
    wmma::fill_fragment(c1, 0.f);

    for (int k = 0; k < C_; k += 16) {
        wmma::load_matrix_sync(ah, XH + m0 * PXB + k, PXB);
        wmma::load_matrix_sync(al, XL + m0 * PXB + k, PXB);
        wmma::load_matrix_sync(bh0, WH + n0 * PXB + k, PXB);
        wmma::load_matrix_sync(bh1, WH + (n0 + 16) * PXB + k, PXB);
        wmma::load_matrix_sync(bl0, WL + n0 * PXB + k, PXB);
        wmma::load_matrix_sync(bl1, WL + (n0 + 16) * PXB + k, PXB);
        wmma::mma_sync(c0, ah, bh0, c0);
        wmma::mma_sync(c0, ah, bl0, c0);
        wmma::mma_sync(c0, al, bh0, c0);
        wmma::mma_sync(c1, ah, bh1, c1);
        wmma::mma_sync(c1, ah, bl1, c1);
        wmma::mma_sync(c1, al, bh1, c1);
    }
    __syncthreads();   // all frag reads done before smem reuse

    float* Cs = (float*)smc;           // [64][68]
    wmma::store_matrix_sync(Cs + m0 * 68 + n0, c0, 68, wmma::mem_row_major);
    wmma::store_matrix_sync(Cs + m0 * 68 + n0 + 16, c1, 68, wmma::mem_row_major);
    __syncthreads();

    // Epilogue: thread handles row = t>>2, local cols 16*(t&3)..+15 (2 groups)
    {
        const int row = t >> 2, seg = t & 3;
        const float* cr = Cs + row * 68 + seg * 16;
        const size_t r = (size_t)b * R + row0 + row;
        const int Gb = (col0 >> 3) + seg * 2;
#pragma unroll
        for (int gi = 0; gi < 2; gi++) {
            float f0 = cr[8 * gi + 0], f1 = cr[8 * gi + 1];
            float f2 = cr[8 * gi + 2], f3 = cr[8 * gi + 3];
            __half2 h0 = __floats2half2_rn(f0, f1);
            __half2 h1 = __floats2half2_rn(f2, f3);
            uint2 pk = make_uint2(*reinterpret_cast<unsigned int*>(&h0),
                                  *reinterpret_cast<unsigned int*>(&h1));
            *(uint2*)(outh + r * 128 + 4 * (Gb + gi)) = pk;
            float4 tq = make_float4(tanhf_fast(cr[8 * gi + 4]),
                                    tanhf_fast(cr[8 * gi + 5]),
                                    tanhf_fast(cr[8 * gi + 6]),
                                    tanhf_fast(cr[8 * gi + 7]));
            *(float4*)(outf + r * 128 + 4 * (Gb + gi)) = tq;
        }
    }
}

// ---------------------------------------------------------------------------
// Scores, warp-specialized 4+4 (unchanged from R12).
// ---------------------------------------------------------------------------
#define EPH_O 0
#define DPH_O (EPH_O + 64 * 66)
#define EPF_O (DPH_O + 32 * 66)
#define DPF_O (EPF_O + 64 * 132)
#define VH_O  (DPF_O + 32 * 132)
#define VFN_O (VH_O + 64)
#define PS_O  (VFN_O + 128)
#define SCORES_SMEM ((PS_O + 2048) * 4)

__global__ __launch_bounds__(256, 2) void scores_kernel(const float* __restrict__ v_g) {
    extern __shared__ unsigned int smu[];
    unsigned int* eph = smu + EPH_O;
    unsigned int* dph = smu + DPH_O;
    float*        epf = (float*)(smu + EPF_O);
    float*        dpf = (float*)(smu + DPF_O);
    unsigned int* vh  = smu + VH_O;
    float*        vfn = (float*)(smu + VFN_O);
    float*        ps  = (float*)(smu + PS_O);

    const int b  = blockIdx.z;
    const int d0 = blockIdx.y * 32;
    const int e0 = blockIdx.x * 64;
    const int t  = threadIdx.x;

    const __half* ehsrc = g_enc_h + ((size_t)b * E_ + e0) * 128;
    for (int i = t; i < 64 * 32; i += 256) {
        int r = i >> 5, q = i & 31;
        uint2 s = ((const uint2*)ehsrc)[r * 32 + q];
        *(uint2*)(eph + r * 66 + q * 2) = s;
    }
    const __half* dhsrc = g_dec_h + ((size_t)b * D_ + d0) * 128;
    for (int i = t; i < 32 * 32; i += 256) {
        int r = i >> 5, q = i & 31;
        uint2 s = ((const uint2*)dhsrc)[r * 32 + q];
        *(uint2*)(dph + r * 66 + q * 2) = s;
    }
    const float* efsrc = g_enc_f + ((size_t)b * E_ + e0) * 128;
    for (int i = t; i < 64 * 32; i += 256) {
        int r = i >> 5, q = i & 31;
        uint4 s = ((const uint4*)efsrc)[r * 32 + q];
        *(uint4*)(epf + r * 132 + q * 4) = s;
    }
    const float* dfsrc = g_dec_f + ((size_t)b * D_ + d0) * 128;
    for (int i = t; i < 32 * 32; i += 256) {
        int r = i >> 5, q = i & 31;
        uint4 s = ((const uint4*)dfsrc)[r * 32 + q];
        *(uint4*)(dpf + r * 132 + q * 4) = s;
    }
    if (t < 64) {
        int g = t >> 1, h = t & 1;
        __half2 p = __floats2half2_rn(v_g[8 * g + 2 * h], v_g[8 * g + 2 * h + 1]);
        vh[t] = *reinterpret_cast<unsigned int*>(&p);
    }
    if (t < 128) {
        vfn[t] = -v_g[8 * (t >> 2) + 4 + (t & 3)];
    }
    __syncthreads();

    const int w  = t >> 5;
    const int el = t & 31;

    if (w < 4) {
        const unsigned int* eh0 = eph + el * 66;
        const unsigned int* eh1 = eph + (el + 32) * 66;
        const unsigned int* dhb = dph + (8 * w) * 66;

        __half2 ah[16];
        float facc[16];
#pragma unroll
        for (int p = 0; p < 16; p++) {
            ah[p] = __floats2half2_rn(0.f, 0.f);
            facc[p] = 0.f;
        }
        for (int g = 0; g < 32; g++) {
            uint2 vv = *(const uint2*)(vh + 2 * g);
            __half2 v0 = u2h(vv.x), v1 = u2h(vv.y);
            uint2 ea = *(const uint2*)(eh0 + 2 * g);
            uint2 eb = *(const uint2*)(eh1 + 2 * g);
            __half2 ea0 = u2h(ea.x), ea1 = u2h(ea.y);
            __half2 eb0 = u2h(eb.x), eb1 = u2h(eb.y);
#pragma unroll
            for (int i = 0; i < 8; i++) {
                uint2 dhp = *(const uint2*)(dhb + i * 66 + 2 * g);
                __half2 dh0 = u2h(dhp.x), dh1 = u2h(dhp.y);
                __half2 s0 = ah[i * 2];
                s0 = __hfma2(tanh2h(__hadd2(dh0, ea0)), v0, s0);
                s0 = __hfma2(tanh2h(__hadd2(dh1, ea1)), v1, s0);
                ah[i * 2] = s0;
                __half2 s1 = ah[i * 2 + 1];
                s1 = __hfma2(tanh2h(__hadd2(dh0, eb0)), v0, s1);
                s1 = __hfma2(tanh2h(__hadd2(dh1, eb1)), v1, s1);
                ah[i * 2 + 1] = s1;
            }
            if ((g & 3) == 3) {
#pragma unroll
                for (int p = 0; p < 16; p++) {
                    float2 f = __half22float2(ah[p]);
                    facc[p] += f.x + f.y;
                    ah[p] = __floats2half2_rn(0.f, 0.f);
                }
            }
        }
#pragma unroll
        for (int i = 0; i < 8; i++) {
            ps[(8 * w + i) * 64 + el]      = facc[i * 2];
            ps[(8 * w + i) * 64 + el + 32] = facc[i * 2 + 1];
        }
    } else {
        const int w4 = w - 4;
        const float* ef0 = epf + el * 132;
        const float* ef1 = epf + (el + 32) * 132;
        const float* dfb = dpf + (8 * w4) * 132;

        ull af[16];
#pragma unroll
        for (int p = 0; p < 16; p++) af[p] = 0ull;

        for (int g = 0; g < 32; g++) {
            uint4 nvq = *(const uint4*)(vfn + 4 * g);
            ull nv0 = pku(nvq.x, nvq.y);
            ull nv1 = pku(nvq.z, nvq.w);
            uint4 e0q = *(const uint4*)(ef0 + 4 * g);
            uint4 e1q = *(const uint4*)(ef1 + 4 * g);
            ull e0a = pku(e0q.x, e0q.y), e0b = pku(e0q.z, e0q.w);
            ull e1a = pku(e1q.x, e1q.y), e1b = pku(e1q.z, e1q.w);
#pragma unroll
            for (int i = 0; i < 8; i++) {
                uint4 dq = *(const uint4*)(dfb + i * 132 + 4 * g);
                ull da = pku(dq.x, dq.y), db = pku(dq.z, dq.w);
                ull a0 = af[i * 2];
                a0 = tanh_sum_acc1(da, e0a, nv0, a0);
                a0 = tanh_sum_acc1(db, e0b, nv1, a0);
                af[i * 2] = a0;
                ull a1 = af[i * 2 + 1];
                a1 = tanh_sum_acc1(da, e1a, nv0, a1);
                a1 = tanh_sum_acc1(db, e1b, nv1, a1);
                af[i * 2 + 1] = a1;
            }
        }
        __syncthreads();
#pragma unroll
        for (int i = 0; i < 8; i++) {
            float lo0, hi0, lo1, hi1;
            asm("mov.b64 {%0, %1}, %2;" : "=f"(lo0), "=f"(hi0) : "l"(af[i * 2]));
            asm("mov.b64 {%0, %1}, %2;" : "=f"(lo1), "=f"(hi1) : "l"(af[i * 2 + 1]));
            float m0 = ps[(8 * w4 + i) * 64 + el];
            float m1 = ps[(8 * w4 + i) * 64 + el + 32];
            float* srow = g_scores + ((size_t)b * D_ + d0 + 8 * w4 + i) * E_ + e0 + el;
            srow[0]  = m0 + lo0 + hi0;
            srow[32] = m1 + lo1 + hi1;
        }
        return;
    }
    __syncthreads();
}

// ---------------------------------------------------------------------------
// Masked log-softmax, one warp per row (unchanged).
// ---------------------------------------------------------------------------
__global__ __launch_bounds__(256) void softmax_kernel(const int* __restrict__ mask,
                                                      float* __restrict__ out) {
    const int row  = blockIdx.x * 8 + (threadIdx.x >> 5);
    const int lane = threadIdx.x & 31;

    const float4* s = (const float4*)(g_scores + (size_t)row * E_);
    const int4*   m = (const int4*)(mask + (size_t)row * E_);

    float x[16];
    float vmax = -3.0e38f;
#pragma unroll
    for (int q = 0; q < 4; q++) {
        float4 sv = s[q * 32 + lane];
        int4   mv = m[q * 32 + lane];
        x[4 * q + 0] = mv.x ? sv.x : NEG_INF;
        x[4 * q + 1] = mv.y ? sv.y : NEG_INF;
        x[4 * q + 2] = mv.z ? sv.z : NEG_INF;
        x[4 * q + 3] = mv.w ? sv.w : NEG_INF;
        vmax = fmaxf(vmax, fmaxf(fmaxf(x[4 * q], x[4 * q + 1]),
                                 fmaxf(x[4 * q + 2], x[4 * q + 3])));
    }
#pragma unroll
    for (int o = 16; o; o >>= 1)
        vmax = fmaxf(vmax, __shfl_xor_sync(0xffffffffu, vmax, o));

    float sum = 0.f;
#pragma unroll
    for (int k = 0; k < 16; k++) sum += __expf(x[k] - vmax);
#pragma unroll
    for (int o = 16; o; o >>= 1)
        sum += __shfl_xor_sync(0xffffffffu, sum, o);

    const float lse = vmax + logf(sum);

    float* orow = out + (size_t)row * E_;
#pragma unroll
    for (int q = 0; q < 4; q++) {
        float4 o4 = make_float4(x[4 * q] - lse, x[4 * q + 1] - lse,
                                x[4 * q + 2] - lse, x[4 * q + 3] - lse);
        ((float4*)orow)[q * 32 + lane] = o4;
    }
}

// ---------------------------------------------------------------------------
extern "C" void kernel_launch(void* const* d_in, const int* in_sizes, int n_in,
                              void* d_out, int out_size) {
    const float* decoder = (const float*)d_in[0];
    const float* encoder = (const float*)d_in[1];
    const int*   mask    = (const int*)d_in[2];
    const float* W1      = (const float*)d_in[3];
    const float* W2      = (const float*)d_in[4];
    const float* v       = (const float*)d_in[5];
    float* out           = (float*)d_out;

    cudaFuncSetAttribute(gemm_tc_kernel,
                         cudaFuncAttributeMaxDynamicSharedMemorySize, GEMM_SMEM);
    cudaFuncSetAttribute(scores_kernel,
                         cudaFuncAttributeMaxDynamicSharedMemorySize, SCORES_SMEM);

    gemm_tc_kernel<<<dim3(4, 48, 1), 256, GEMM_SMEM>>>(encoder, decoder, W1, W2);
    scores_kernel<<<dim3(E_ / 64, D_ / 32, B_), 256, SCORES_SMEM>>>(v);
    softmax_kernel<<<B_ * D_ / 8, 256>>>(mask, out);
}

// round 15
// speedup vs baseline: 1.4197x; 1.4197x over previous
#include <cuda_runtime.h>
#include <cuda_fp16.h>
#include <cuda_bf16.h>
#include <cstddef>
#include <cstdint>

#define B_   4
#define D_   256
#define E_   512
#define C_   256
#define NEG_INF -1e9f

typedef unsigned long long ull;

// Scratch. h buffers: proj as half for c%8 in {0..3}: row = 128 halves,
// position (c>>3)*4 + (c&3). f buffers: tanh(proj) as f32 for c%8 in {4..7}.
__device__ __half g_enc_h[B_ * E_ * 128];
__device__ float  g_enc_f[B_ * E_ * 128];
__device__ __half g_dec_h[B_ * D_ * 128];
__device__ float  g_dec_f[B_ * D_ * 128];

__device__ __forceinline__ __half2 tanh2h(__half2 x) {
    unsigned int r, xi = *reinterpret_cast<unsigned int*>(&x);
    asm("tanh.approx.f16x2 %0, %1;" : "=r"(r) : "r"(xi));
    return *reinterpret_cast<__half2*>(&r);
}
__device__ __forceinline__ __half2 u2h(unsigned int u) {
    return *reinterpret_cast<__half2*>(&u);
}
__device__ __forceinline__ float tanhf_fast(float x) {
    float y; asm("tanh.approx.f32 %0, %1;" : "=f"(y) : "f"(x)); return y;
}
__device__ __forceinline__ ull fma2_(ull a, ull b, ull c) {
    ull d; asm("fma.rn.f32x2 %0, %1, %2, %3;" : "=l"(d) : "l"(a), "l"(b), "l"(c)); return d;
}
__device__ __forceinline__ ull add2_(ull a, ull b) {
    ull d; asm("add.rn.f32x2 %0, %1, %2;" : "=l"(d) : "l"(a), "l"(b)); return d;
}
__device__ __forceinline__ ull mul2_(ull a, ull b) {
    ull d; asm("mul.rn.f32x2 %0, %1, %2;" : "=l"(d) : "l"(a), "l"(b)); return d;
}

#define ONE2_  0x3F8000003F800000ull
#define NTWO2_ 0xC0000000C0000000ull

__device__ __forceinline__ ull tanh_sum_acc1(ull ta, ull tb, ull nv, ull acc) {
    ull num = add2_(ta, tb);
    ull den = fma2_(ta, tb, ONE2_);          // 1 + ta*tb in (0,2]
    ull r0;
    asm("{\n\t.reg .b32 lo, hi;\n\t"
        "mov.b64 {lo, hi}, %1;\n\t"
        "sub.u32 lo, 0x7EF311C3, lo;\n\t"
        "sub.u32 hi, 0x7EF311C3, hi;\n\t"
        "mov.b64 %0, {lo, hi};\n\t}" : "=l"(r0) : "l"(den));
    ull u1  = fma2_(den, r0, NTWO2_);
    ull r1n = mul2_(r0, u1);                 // -1/den
    ull t   = mul2_(num, r1n);               // -tanh(a+b)
    return fma2_(t, nv, acc);
}
__device__ __forceinline__ ull pku(unsigned lo, unsigned hi) {
    return ((ull)hi << 32) | lo;
}

// ---------------------------------------------------------------------------
// Fused GEMM (R12, measured 18.5us): tile 64x32, BK=16, 128 thr, 4x4 micro.
// Epilogue 4:4 split: tx even -> 4 halves (c%8 0..3) to h buffer;
// tx odd -> 4 tanh'd f32 (c%8 4..7) to f buffer.
// ---------------------------------------------------------------------------
__global__ __launch_bounds__(128) void gemm_fused_kernel(
        const float* __restrict__ enc, const float* __restrict__ dec,
        const float* __restrict__ W1,  const float* __restrict__ W2) {
    __shared__ float Xs[16][68];
    __shared__ float Ws[16][36];

    const int b  = blockIdx.z;
    const int yt = blockIdx.y;
    const bool is_enc = (yt < 8);
    const int R      = is_enc ? E_ : D_;
    const int row0   = (is_enc ? yt : yt - 8) * 64;
    const int col0   = blockIdx.x * 32;
    const float* X   = is_enc ? enc : dec;
    const float* W   = is_enc ? W1  : W2;
    __half* outh     = is_enc ? g_enc_h : g_dec_h;
    float*  outf     = is_enc ? g_enc_f : g_dec_f;

    const int t  = threadIdx.x;
    const int lr = t >> 2;
    const int lc = (t & 3) << 2;
    const int ty = t >> 3;
    const int tx = t & 7;

    const float* Xb = X + ((size_t)b * R + row0 + lr) * C_ + lc;
    const float* Wb = W + (size_t)(col0 + lr) * C_ + lc;

    float4 xa0 = *(const float4*)Xb;
    float4 xa1 = *(const float4*)(Xb + 32 * C_);
    float4 wa  = *(const float4*)Wb;

    float acc[4][4];
#pragma unroll
    for (int i = 0; i < 4; i++)
#pragma unroll
        for (int j = 0; j < 4; j++) acc[i][j] = 0.f;

    for (int k0 = 0; k0 < C_; k0 += 16) {
        Xs[lc + 0][lr] = xa0.x; Xs[lc + 1][lr] = xa0.y;
        Xs[lc + 2][lr] = xa0.z; Xs[lc + 3][lr] = xa0.w;
        Xs[lc + 0][lr + 32] = xa1.x; Xs[lc + 1][lr + 32] = xa1.y;
        Xs[lc + 2][lr + 32] = xa1.z; Xs[lc + 3][lr + 32] = xa1.w;
        Ws[lc + 0][lr] = wa.x; Ws[lc + 1][lr] = wa.y;
        Ws[lc + 2][lr] = wa.z; Ws[lc + 3][lr] = wa.w;
        __syncthreads();
        if (k0 + 16 < C_) {
            xa0 = *(const float4*)(Xb + k0 + 16);
            xa1 = *(const float4*)(Xb + 32 * C_ + k0 + 16);
            wa  = *(const float4*)(Wb + k0 + 16);
        }
#pragma unroll
        for (int kk = 0; kk < 16; kk++) {
            float4 a4 = *(const float4*)&Xs[kk][ty * 4];
            float4 b4 = *(const float4*)&Ws[kk][tx * 4];
            float a[4] = {a4.x, a4.y, a4.z, a4.w};
            float bb[4] = {b4.x, b4.y, b4.z, b4.w};
#pragma unroll
            for (int i = 0; i < 4; i++)
#pragma unroll
                for (int j = 0; j < 4; j++)
                    acc[i][j] = fmaf(a[i], bb[j], acc[i][j]);
        }
        __syncthreads();
    }

    const int G = (col0 >> 3) + (tx >> 1);
#pragma unroll
    for (int i = 0; i < 4; i++) {
        const size_t r = (size_t)b * R + row0 + ty * 4 + i;
        if ((tx & 1) == 0) {
            __half2 h0 = __floats2half2_rn(acc[i][0], acc[i][1]);
            __half2 h1 = __floats2half2_rn(acc[i][2], acc[i][3]);
            uint2 pk = make_uint2(*reinterpret_cast<unsigned int*>(&h0),
                                  *reinterpret_cast<unsigned int*>(&h1));
            *(uint2*)(outh + r * 128 + 4 * G) = pk;
        } else {
            float4 tq = make_float4(tanhf_fast(acc[i][0]), tanhf_fast(acc[i][1]),
                                    tanhf_fast(acc[i][2]), tanhf_fast(acc[i][3]));
            *(float4*)(outf + r * 128 + 4 * G) = tq;
        }
    }
}

// ---------------------------------------------------------------------------
// Fused scores + log-softmax. CTA = 4 d rows x full 512 e, 256 thr.
// e processed in 8 chunks of 64 (enc smem refilled per chunk).
// Warps 0-3: MUFU path (c%8 0..3, h2), warp w owns d row w, e = el/el+32.
// Warps 4-7: FMA path (c%8 4..7, f32 addition formula), row w-4.
// Scores collected in smem ps_m/ps_f (each (d,e) written once), then
// in-CTA masked log-softmax (warps 0-3, one row each) writes output.
// grid: (64 d-tiles, B). No g_scores round-trip, no softmax kernel.
// ---------------------------------------------------------------------------
#define F_DPH 0
#define F_DPF (F_DPH + 4 * 66)        // 264
#define F_EPH (F_DPF + 4 * 132)       // 792
#define F_EPF (F_EPH + 64 * 66)       // 5016
#define F_VH  (F_EPF + 64 * 132)      // 13464
#define F_VFN (F_VH + 64)             // 13528
#define F_PSM (F_VFN + 128)           // 13656
#define F_PSF (F_PSM + 4 * 512)       // 15704
#define FUSED_SMEM ((F_PSF + 4 * 512) * 4)   // 71008 B

__global__ __launch_bounds__(256) void fused_kernel(
        const float* __restrict__ v_g, const int* __restrict__ mask,
        float* __restrict__ out) {
    extern __shared__ unsigned int smu[];
    unsigned int* dph = smu + F_DPH;            // 4 x 66 (h2, pitch 66)
    float*        dpf = (float*)(smu + F_DPF);  // 4 x 132
    unsigned int* eph = smu + F_EPH;            // 64 x 66
    float*        epf = (float*)(smu + F_EPF);  // 64 x 132
    unsigned int* vh  = smu + F_VH;             // 64 h2 words
    float*        vfn = (float*)(smu + F_VFN);  // 128 f32 (-v)
    float*        psm = (float*)(smu + F_PSM);  // 4 x 512
    float*        psf = (float*)(smu + F_PSF);  // 4 x 512

    const int b  = blockIdx.y;
    const int d0 = blockIdx.x * 4;
    const int t  = threadIdx.x;
    const int w  = t >> 5;
    const int el = t & 31;

    // One-time fills: dec rows + v
    const __half* dhsrc = g_dec_h + ((size_t)b * D_ + d0) * 128;
    for (int i = t; i < 4 * 32; i += 256) {
        int r = i >> 5, q = i & 31;
        uint2 s = ((const uint2*)dhsrc)[r * 32 + q];
        *(uint2*)(dph + r * 66 + q * 2) = s;
    }
    const float* dfsrc = g_dec_f + ((size_t)b * D_ + d0) * 128;
    if (t < 4 * 32) {
        int r = t >> 5, q = t & 31;
        uint4 s = ((const uint4*)dfsrc)[r * 32 + q];
        *(uint4*)(dpf + r * 132 + q * 4) = s;
    }
    if (t < 64) {
        int g = t >> 1, h = t & 1;
        __half2 p = __floats2half2_rn(v_g[8 * g + 2 * h], v_g[8 * g + 2 * h + 1]);
        vh[t] = *reinterpret_cast<unsigned int*>(&p);
    }
    if (t < 128) {
        vfn[t] = -v_g[8 * (t >> 2) + 4 + (t & 3)];
    }

    for (int chunk = 0; chunk < 8; chunk++) {
        const int e0 = chunk * 64;
        __syncthreads();   // prior chunk's readers done before refill
        const __half* ehsrc = g_enc_h + ((size_t)b * E_ + e0) * 128;
        for (int i = t; i < 64 * 32; i += 256) {
            int r = i >> 5, q = i & 31;
            uint2 s = ((const uint2*)ehsrc)[r * 32 + q];
            *(uint2*)(eph + r * 66 + q * 2) = s;
        }
        const float* efsrc = g_enc_f + ((size_t)b * E_ + e0) * 128;
        for (int i = t; i < 64 * 32; i += 256) {
            int r = i >> 5, q = i & 31;
            uint4 s = ((const uint4*)efsrc)[r * 32 + q];
            *(uint4*)(epf + r * 132 + q * 4) = s;
        }
        __syncthreads();

        if (w < 4) {
            // MUFU warp: row w, e = el / el+32
            const unsigned int* eh0 = eph + el * 66;
            const unsigned int* eh1 = eph + (el + 32) * 66;
            const unsigned int* dhr = dph + w * 66;
            __half2 a0 = __floats2half2_rn(0.f, 0.f);
            __half2 a1 = a0;
            float f0 = 0.f, f1 = 0.f;
#pragma unroll 4
            for (int g = 0; g < 32; g++) {
                uint2 vv  = *(const uint2*)(vh + 2 * g);
                uint2 dh  = *(const uint2*)(dhr + 2 * g);
                uint2 ea  = *(const uint2*)(eh0 + 2 * g);
                uint2 eb  = *(const uint2*)(eh1 + 2 * g);
                __half2 v0 = u2h(vv.x), v1 = u2h(vv.y);
                __half2 d0h = u2h(dh.x), d1h = u2h(dh.y);
                a0 = __hfma2(tanh2h(__hadd2(d0h, u2h(ea.x))), v0, a0);
                a0 = __hfma2(tanh2h(__hadd2(d1h, u2h(ea.y))), v1, a0);
                a1 = __hfma2(tanh2h(__hadd2(d0h, u2h(eb.x))), v0, a1);
                a1 = __hfma2(tanh2h(__hadd2(d1h, u2h(eb.y))), v1, a1);
                if ((g & 3) == 3) {
                    float2 p0 = __half22float2(a0);
                    float2 p1 = __half22float2(a1);
                    f0 += p0.x + p0.y;
                    f1 += p1.x + p1.y;
                    a0 = __floats2half2_rn(0.f, 0.f);
                    a1 = a0;
                }
            }
            psm[w * 512 + e0 + el]      = f0;
            psm[w * 512 + e0 + el + 32] = f1;
        } else {
            // FMA warp: row w-4
            const int row = w - 4;
            const float* ef0 = epf + el * 132;
            const float* ef1 = epf + (el + 32) * 132;
            const float* dfr = dpf + row * 132;
            ull A0 = 0ull, A1 = 0ull;
#pragma unroll 4
            for (int g = 0; g < 32; g++) {
                uint4 nvq = *(const uint4*)(vfn + 4 * g);
                ull nv0 = pku(nvq.x, nvq.y), nv1 = pku(nvq.z, nvq.w);
                uint4 dq = *(const uint4*)(dfr + 4 * g);
                ull da = pku(dq.x, dq.y), db = pku(dq.z, dq.w);
                uint4 e0q = *(const uint4*)(ef0 + 4 * g);
                uint4 e1q = *(const uint4*)(ef1 + 4 * g);
                A0 = tanh_sum_acc1(da, pku(e0q.x, e0q.y), nv0, A0);
                A0 = tanh_sum_acc1(db, pku(e0q.z, e0q.w), nv1, A0);
                A1 = tanh_sum_acc1(da, pku(e1q.x, e1q.y), nv0, A1);
                A1 = tanh_sum_acc1(db, pku(e1q.z, e1q.w), nv1, A1);
            }
            float lo0, hi0, lo1, hi1;
            asm("mov.b64 {%0, %1}, %2;" : "=f"(lo0), "=f"(hi0) : "l"(A0));
            asm("mov.b64 {%0, %1}, %2;" : "=f"(lo1), "=f"(hi1) : "l"(A1));
            psf[row * 512 + e0 + el]      = lo0 + hi0;
            psf[row * 512 + e0 + el + 32] = lo1 + hi1;
        }
    }
    __syncthreads();

    // In-CTA masked log-softmax: warps 0-3, one full 512-e row each.
    if (w < 4) {
        const size_t grow = (size_t)b * D_ + d0 + w;
        const float4* pm4 = (const float4*)(psm + w * 512);
        const float4* pf4 = (const float4*)(psf + w * 512);
        const int4*   m4  = (const int4*)(mask + grow * E_);

        float x[16];
        float vmax = -3.0e38f;
#pragma unroll
        for (int q = 0; q < 4; q++) {
            float4 sm = pm4[q * 32 + el];
            float4 sf = pf4[q * 32 + el];
            int4   mv = m4[q * 32 + el];
            x[4 * q + 0] = mv.x ? (sm.x + sf.x) : NEG_INF;
            x[4 * q + 1] = mv.y ? (sm.y + sf.y) : NEG_INF;
            x[4 * q + 2] = mv.z ? (sm.z + sf.z) : NEG_INF;
            x[4 * q + 3] = mv.w ? (sm.w + sf.w) : NEG_INF;
            vmax = fmaxf(vmax, fmaxf(fmaxf(x[4 * q], x[4 * q + 1]),
                                     fmaxf(x[4 * q + 2], x[4 * q + 3])));
        }
#pragma unroll
        for (int o = 16; o; o >>= 1)
            vmax = fmaxf(vmax, __shfl_xor_sync(0xffffffffu, vmax, o));

        float sum = 0.f;
#pragma unroll
        for (int k = 0; k < 16; k++) sum += __expf(x[k] - vmax);
#pragma unroll
        for (int o = 16; o; o >>= 1)
            sum += __shfl_xor_sync(0xffffffffu, sum, o);

        const float lse = vmax + logf(sum);

        float* orow = out + grow * E_;
#pragma unroll
        for (int q = 0; q < 4; q++) {
            float4 o4 = make_float4(x[4 * q] - lse, x[4 * q + 1] - lse,
                                    x[4 * q + 2] - lse, x[4 * q + 3] - lse);
            ((float4*)orow)[q * 32 + el] = o4;
        }
    }
}

// ---------------------------------------------------------------------------
extern "C" void kernel_launch(void* const* d_in, const int* in_sizes, int n_in,
                              void* d_out, int out_size) {
    const float* decoder = (const float*)d_in[0];
    const float* encoder = (const float*)d_in[1];
    const int*   mask    = (const int*)d_in[2];
    const float* W1      = (const float*)d_in[3];
    const float* W2      = (const float*)d_in[4];
    const float* v       = (const float*)d_in[5];
    float* out           = (float*)d_out;

    cudaFuncSetAttribute(fused_kernel,
                         cudaFuncAttributeMaxDynamicSharedMemorySize, FUSED_SMEM);

    gemm_fused_kernel<<<dim3(8, 12, B_), 128>>>(encoder, decoder, W1, W2);
    fused_kernel<<<dim3(D_ / 4, B_), 256, FUSED_SMEM>>>(v, mask, out);
}

// round 16
// speedup vs baseline: 1.7925x; 1.2626x over previous
#include <cuda_runtime.h>
#include <cuda_fp16.h>
#include <cuda_bf16.h>
#include <mma.h>
#include <cstddef>
#include <cstdint>

using namespace nvcuda;

#define B_   4
#define D_   256
#define E_   512
#define C_   256
#define NEG_INF -1e9f

typedef unsigned long long ull;

// Scratch. h buffers: proj as half for c%8 in {0..3}: row = 128 halves,
// position (c>>3)*4 + (c&3). f buffers: tanh(proj) as f32 for c%8 in {4..7}.
__device__ __half g_enc_h[B_ * E_ * 128];
__device__ float  g_enc_f[B_ * E_ * 128];
__device__ __half g_dec_h[B_ * D_ * 128];
__device__ float  g_dec_f[B_ * D_ * 128];
__device__ float  g_scores[B_ * D_ * E_];

__device__ __forceinline__ __half2 tanh2h(__half2 x) {
    unsigned int r, xi = *reinterpret_cast<unsigned int*>(&x);
    asm("tanh.approx.f16x2 %0, %1;" : "=r"(r) : "r"(xi));
    return *reinterpret_cast<__half2*>(&r);
}
__device__ __forceinline__ __half2 u2h(unsigned int u) {
    return *reinterpret_cast<__half2*>(&u);
}
__device__ __forceinline__ float tanhf_fast(float x) {
    float y; asm("tanh.approx.f32 %0, %1;" : "=f"(y) : "f"(x)); return y;
}
__device__ __forceinline__ ull fma2_(ull a, ull b, ull c) {
    ull d; asm("fma.rn.f32x2 %0, %1, %2, %3;" : "=l"(d) : "l"(a), "l"(b), "l"(c)); return d;
}
__device__ __forceinline__ ull add2_(ull a, ull b) {
    ull d; asm("add.rn.f32x2 %0, %1, %2;" : "=l"(d) : "l"(a), "l"(b)); return d;
}
__device__ __forceinline__ ull mul2_(ull a, ull b) {
    ull d; asm("mul.rn.f32x2 %0, %1, %2;" : "=l"(d) : "l"(a), "l"(b)); return d;
}

#define ONE2_  0x3F8000003F800000ull
#define NTWO2_ 0xC0000000C0000000ull

__device__ __forceinline__ ull tanh_sum_acc1(ull ta, ull tb, ull nv, ull acc) {
    ull num = add2_(ta, tb);
    ull den = fma2_(ta, tb, ONE2_);          // 1 + ta*tb in (0,2]
    ull r0;
    asm("{\n\t.reg .b32 lo, hi;\n\t"
        "mov.b64 {lo, hi}, %1;\n\t"
        "sub.u32 lo, 0x7EF311C3, lo;\n\t"
        "sub.u32 hi, 0x7EF311C3, hi;\n\t"
        "mov.b64 %0, {lo, hi};\n\t}" : "=l"(r0) : "l"(den));
    ull u1  = fma2_(den, r0, NTWO2_);
    ull r1n = mul2_(r0, u1);                 // -1/den
    ull t   = mul2_(num, r1n);               // -tanh(a+b)
    return fma2_(t, nv, acc);
}
__device__ __forceinline__ ull pku(unsigned lo, unsigned hi) {
    return ((ull)hi << 32) | lo;
}

// ---------------------------------------------------------------------------
// Lean wmma GEMM: 64 rows x 32 cols per CTA, BK=64 staged, 128 thr (4 warps).
// Hi/lo bf16 split: D = Ah*Bh + Ah*Bl + Al*Bh. Static smem 36.8KB -> ~6 CTA/SM.
// Warp w: rows 16w..16w+15, full 32 cols (2 accum frags).
// grid: (8 col tiles, 12 row tiles [0..7 enc, 8..11 dec], B).
// Epilogue: C -> smem -> h2 buffer (c%8 0..3) + tanh'd f32 (c%8 4..7).
// ---------------------------------------------------------------------------
#define PW 72   // bf16 pitch for stage tiles

__global__ __launch_bounds__(128) void gemm_wmma_kernel(
        const float* __restrict__ enc, const float* __restrict__ dec,
        const float* __restrict__ W1,  const float* __restrict__ W2) {
    __shared__ __nv_bfloat16 XH[64][PW], XL[64][PW];
    __shared__ __nv_bfloat16 WH[32][PW], WL[32][PW];
    __shared__ float Cs[64][36];

    const int t = threadIdx.x;
    const int w = t >> 5;
    const int b  = blockIdx.z;
    const int yt = blockIdx.y;
    const bool is_enc = (yt < 8);
    const int R      = is_enc ? E_ : D_;
    const int row0   = (is_enc ? yt : yt - 8) * 64;
    const int col0   = blockIdx.x * 32;
    const float* X   = is_enc ? enc : dec;
    const float* W   = is_enc ? W1  : W2;
    __half* outh     = is_enc ? g_enc_h : g_dec_h;
    float*  outf     = is_enc ? g_enc_f : g_dec_f;

    const float* Xb = X + ((size_t)b * R + row0) * C_;
    const float* Wb = W + (size_t)col0 * C_;

    wmma::fragment<wmma::matrix_a, 16, 16, 16, __nv_bfloat16, wmma::row_major> ah, al;
    wmma::fragment<wmma::matrix_b, 16, 16, 16, __nv_bfloat16, wmma::col_major> bh0, bh1, bl0, bl1;
    wmma::fragment<wmma::accumulator, 16, 16, 16, float> c0, c1;
    wmma::fill_fragment(c0, 0.f);
    wmma::fill_fragment(c1, 0.f);

    for (int k0 = 0; k0 < C_; k0 += 64) {
        __syncthreads();   // prior stage's frag loads complete
        // Fill X stage: 64 rows x 64 k  (1024 float4 loads)
        for (int i = t; i < 64 * 16; i += 128) {
            int row = i >> 4, cq = (i & 15) << 2;
            float4 x = *(const float4*)(Xb + row * C_ + k0 + cq);
            float fx[4] = {x.x, x.y, x.z, x.w};
            unsigned short hb[4], lb[4];
#pragma unroll
            for (int j = 0; j < 4; j++) {
                __nv_bfloat16 h = __float2bfloat16(fx[j]);
                hb[j] = *reinterpret_cast<unsigned short*>(&h);
                __nv_bfloat16 l = __float2bfloat16(fx[j] - __bfloat162float(h));
                lb[j] = *reinterpret_cast<unsigned short*>(&l);
            }
            *(uint2*)(&XH[row][cq]) =
                make_uint2((uint32_t)hb[0] | ((uint32_t)hb[1] << 16),
                           (uint32_t)hb[2] | ((uint32_t)hb[3] << 16));
            *(uint2*)(&XL[row][cq]) =
                make_uint2((uint32_t)lb[0] | ((uint32_t)lb[1] << 16),
                           (uint32_t)lb[2] | ((uint32_t)lb[3] << 16));
        }
        // Fill W stage: 32 rows x 64 k
        for (int i = t; i < 32 * 16; i += 128) {
            int row = i >> 4, cq = (i & 15) << 2;
            float4 x = *(const float4*)(Wb + row * C_ + k0 + cq);
            float fx[4] = {x.x, x.y, x.z, x.w};
            unsigned short hb[4], lb[4];
#pragma unroll
            for (int j = 0; j < 4; j++) {
                __nv_bfloat16 h = __float2bfloat16(fx[j]);
                hb[j] = *reinterpret_cast<unsigned short*>(&h);
                __nv_bfloat16 l = __float2bfloat16(fx[j] - __bfloat162float(h));
                lb[j] = *reinterpret_cast<unsigned short*>(&l);
            }
            *(uint2*)(&WH[row][cq]) =
                make_uint2((uint32_t)hb[0] | ((uint32_t)hb[1] << 16),
                           (uint32_t)hb[2] | ((uint32_t)hb[3] << 16));
            *(uint2*)(&WL[row][cq]) =
                make_uint2((uint32_t)lb[0] | ((uint32_t)lb[1] << 16),
                           (uint32_t)lb[2] | ((uint32_t)lb[3] << 16));
        }
        __syncthreads();

#pragma unroll
        for (int kk = 0; kk < 64; kk += 16) {
            wmma::load_matrix_sync(ah, &XH[w * 16][kk], PW);
            wmma::load_matrix_sync(al, &XL[w * 16][kk], PW);
            wmma::load_matrix_sync(bh0, &WH[0][kk],  PW);
            wmma::load_matrix_sync(bh1, &WH[16][kk], PW);
            wmma::load_matrix_sync(bl0, &WL[0][kk],  PW);
            wmma::load_matrix_sync(bl1, &WL[16][kk], PW);
            wmma::mma_sync(c0, ah, bh0, c0);
            wmma::mma_sync(c0, ah, bl0, c0);
            wmma::mma_sync(c0, al, bh0, c0);
            wmma::mma_sync(c1, ah, bh1, c1);
            wmma::mma_sync(c1, ah, bl1, c1);
            wmma::mma_sync(c1, al, bh1, c1);
        }
    }

    wmma::store_matrix_sync(&Cs[w * 16][0],  c0, 36, wmma::mem_row_major);
    wmma::store_matrix_sync(&Cs[w * 16][16], c1, 36, wmma::mem_row_major);
    __syncthreads();

    // Epilogue: thread t -> row = t>>1, seg = t&1 (16 cols each, 2 c-groups)
    {
        const int row = t >> 1, seg = t & 1;
        const float* cr = &Cs[row][seg * 16];
        const size_t r = (size_t)b * R + row0 + row;
        const int Gb = (col0 >> 3) + seg * 2;
#pragma unroll
        for (int gi = 0; gi < 2; gi++) {
            __half2 h0 = __floats2half2_rn(cr[8 * gi + 0], cr[8 * gi + 1]);
            __half2 h1 = __floats2half2_rn(cr[8 * gi + 2], cr[8 * gi + 3]);
            uint2 pk = make_uint2(*reinterpret_cast<unsigned int*>(&h0),
                                  *reinterpret_cast<unsigned int*>(&h1));
            *(uint2*)(outh + r * 128 + 4 * (Gb + gi)) = pk;
            float4 tq = make_float4(tanhf_fast(cr[8 * gi + 4]),
                                    tanhf_fast(cr[8 * gi + 5]),
                                    tanhf_fast(cr[8 * gi + 6]),
                                    tanhf_fast(cr[8 * gi + 7]));
            *(float4*)(outf + r * 128 + 4 * (Gb + gi)) = tq;
        }
    }
}

// ---------------------------------------------------------------------------
// Scores, warp-specialized 4+4 (R12, proven).
// ---------------------------------------------------------------------------
#define EPH_O 0
#define DPH_O (EPH_O + 64 * 66)
#define EPF_O (DPH_O + 32 * 66)
#define DPF_O (EPF_O + 64 * 132)
#define VH_O  (DPF_O + 32 * 132)
#define VFN_O (VH_O + 64)
#define PS_O  (VFN_O + 128)
#define SCORES_SMEM ((PS_O + 2048) * 4)

__global__ __launch_bounds__(256, 2) void scores_kernel(const float* __restrict__ v_g) {
    extern __shared__ unsigned int smu[];
    unsigned int* eph = smu + EPH_O;
    unsigned int* dph = smu + DPH_O;
    float*        epf = (float*)(smu + EPF_O);
    float*        dpf = (float*)(smu + DPF_O);
    unsigned int* vh  = smu + VH_O;
    float*        vfn = (float*)(smu + VFN_O);
    float*        ps  = (float*)(smu + PS_O);

    const int b  = blockIdx.z;
    const int d0 = blockIdx.y * 32;
    const int e0 = blockIdx.x * 64;
    const int t  = threadIdx.x;

    const __half* ehsrc = g_enc_h + ((size_t)b * E_ + e0) * 128;
    for (int i = t; i < 64 * 32; i += 256) {
        int r = i >> 5, q = i & 31;
        uint2 s = ((const uint2*)ehsrc)[r * 32 + q];
        *(uint2*)(eph + r * 66 + q * 2) = s;
    }
    const __half* dhsrc = g_dec_h + ((size_t)b * D_ + d0) * 128;
    for (int i = t; i < 32 * 32; i += 256) {
        int r = i >> 5, q = i & 31;
        uint2 s = ((const uint2*)dhsrc)[r * 32 + q];
        *(uint2*)(dph + r * 66 + q * 2) = s;
    }
    const float* efsrc = g_enc_f + ((size_t)b * E_ + e0) * 128;
    for (int i = t; i < 64 * 32; i += 256) {
        int r = i >> 5, q = i & 31;
        uint4 s = ((const uint4*)efsrc)[r * 32 + q];
        *(uint4*)(epf + r * 132 + q * 4) = s;
    }
    const float* dfsrc = g_dec_f + ((size_t)b * D_ + d0) * 128;
    for (int i = t; i < 32 * 32; i += 256) {
        int r = i >> 5, q = i & 31;
        uint4 s = ((const uint4*)dfsrc)[r * 32 + q];
        *(uint4*)(dpf + r * 132 + q * 4) = s;
    }
    if (t < 64) {
        int g = t >> 1, h = t & 1;
        __half2 p = __floats2half2_rn(v_g[8 * g + 2 * h], v_g[8 * g + 2 * h + 1]);
        vh[t] = *reinterpret_cast<unsigned int*>(&p);
    }
    if (t < 128) {
        vfn[t] = -v_g[8 * (t >> 2) + 4 + (t & 3)];
    }
    __syncthreads();

    const int w  = t >> 5;
    const int el = t & 31;

    if (w < 4) {
        const unsigned int* eh0 = eph + el * 66;
        const unsigned int* eh1 = eph + (el + 32) * 66;
        const unsigned int* dhb = dph + (8 * w) * 66;

        __half2 ah[16];
        float facc[16];
#pragma unroll
        for (int p = 0; p < 16; p++) {
            ah[p] = __floats2half2_rn(0.f, 0.f);
            facc[p] = 0.f;
        }
        for (int g = 0; g < 32; g++) {
            uint2 vv = *(const uint2*)(vh + 2 * g);
            __half2 v0 = u2h(vv.x), v1 = u2h(vv.y);
            uint2 ea = *(const uint2*)(eh0 + 2 * g);
            uint2 eb = *(const uint2*)(eh1 + 2 * g);
            __half2 ea0 = u2h(ea.x), ea1 = u2h(ea.y);
            __half2 eb0 = u2h(eb.x), eb1 = u2h(eb.y);
#pragma unroll
            for (int i = 0; i < 8; i++) {
                uint2 dhp = *(const uint2*)(dhb + i * 66 + 2 * g);
                __half2 dh0 = u2h(dhp.x), dh1 = u2h(dhp.y);
                __half2 s0 = ah[i * 2];
                s0 = __hfma2(tanh2h(__hadd2(dh0, ea0)), v0, s0);
                s0 = __hfma2(tanh2h(__hadd2(dh1, ea1)), v1, s0);
                ah[i * 2] = s0;
                __half2 s1 = ah[i * 2 + 1];
                s1 = __hfma2(tanh2h(__hadd2(dh0, eb0)), v0, s1);
                s1 = __hfma2(tanh2h(__hadd2(dh1, eb1)), v1, s1);
                ah[i * 2 + 1] = s1;
            }
            if ((g & 3) == 3) {
#pragma unroll
                for (int p = 0; p < 16; p++) {
                    float2 f = __half22float2(ah[p]);
                    facc[p] += f.x + f.y;
                    ah[p] = __floats2half2_rn(0.f, 0.f);
                }
            }
        }
#pragma unroll
        for (int i = 0; i < 8; i++) {
            ps[(8 * w + i) * 64 + el]      = facc[i * 2];
            ps[(8 * w + i) * 64 + el + 32] = facc[i * 2 + 1];
        }
    } else {
        const int w4 = w - 4;
        const float* ef0 = epf + el * 132;
        const float* ef1 = epf + (el + 32) * 132;
        const float* dfb = dpf + (8 * w4) * 132;

        ull af[16];
#pragma unroll
        for (int p = 0; p < 16; p++) af[p] = 0ull;

        for (int g = 0; g < 32; g++) {
            uint4 nvq = *(const uint4*)(vfn + 4 * g);
            ull nv0 = pku(nvq.x, nvq.y);
            ull nv1 = pku(nvq.z, nvq.w);
            uint4 e0q = *(const uint4*)(ef0 + 4 * g);
            uint4 e1q = *(const uint4*)(ef1 + 4 * g);
            ull e0a = pku(e0q.x, e0q.y), e0b = pku(e0q.z, e0q.w);
            ull e1a = pku(e1q.x, e1q.y), e1b = pku(e1q.z, e1q.w);
#pragma unroll
            for (int i = 0; i < 8; i++) {
                uint4 dq = *(const uint4*)(dfb + i * 132 + 4 * g);
                ull da = pku(dq.x, dq.y), db = pku(dq.z, dq.w);
                ull a0 = af[i * 2];
                a0 = tanh_sum_acc1(da, e0a, nv0, a0);
                a0 = tanh_sum_acc1(db, e0b, nv1, a0);
                af[i * 2] = a0;
                ull a1 = af[i * 2 + 1];
                a1 = tanh_sum_acc1(da, e1a, nv0, a1);
                a1 = tanh_sum_acc1(db, e1b, nv1, a1);
                af[i * 2 + 1] = a1;
            }
        }
        __syncthreads();
#pragma unroll
        for (int i = 0; i < 8; i++) {
            float lo0, hi0, lo1, hi1;
            asm("mov.b64 {%0, %1}, %2;" : "=f"(lo0), "=f"(hi0) : "l"(af[i * 2]));
            asm("mov.b64 {%0, %1}, %2;" : "=f"(lo1), "=f"(hi1) : "l"(af[i * 2 + 1]));
            float m0 = ps[(8 * w4 + i) * 64 + el];
            float m1 = ps[(8 * w4 + i) * 64 + el + 32];
            float* srow = g_scores + ((size_t)b * D_ + d0 + 8 * w4 + i) * E_ + e0 + el;
            srow[0]  = m0 + lo0 + hi0;
            srow[32] = m1 + lo1 + hi1;
        }
        return;
    }
    __syncthreads();
}

// ---------------------------------------------------------------------------
// Masked log-softmax, one warp per row.
// ---------------------------------------------------------------------------
__global__ __launch_bounds__(256) void softmax_kernel(const int* __restrict__ mask,
                                                      float* __restrict__ out) {
    const int row  = blockIdx.x * 8 + (threadIdx.x >> 5);
    const int lane = threadIdx.x & 31;

    const float4* s = (const float4*)(g_scores + (size_t)row * E_);
    const int4*   m = (const int4*)(mask + (size_t)row * E_);

    float x[16];
    float vmax = -3.0e38f;
#pragma unroll
    for (int q = 0; q < 4; q++) {
        float4 sv = s[q * 32 + lane];
        int4   mv = m[q * 32 + lane];
        x[4 * q + 0] = mv.x ? sv.x : NEG_INF;
        x[4 * q + 1] = mv.y ? sv.y : NEG_INF;
        x[4 * q + 2] = mv.z ? sv.z : NEG_INF;
        x[4 * q + 3] = mv.w ? sv.w : NEG_INF;
        vmax = fmaxf(vmax, fmaxf(fmaxf(x[4 * q], x[4 * q + 1]),
                                 fmaxf(x[4 * q + 2], x[4 * q + 3])));
    }
#pragma unroll
    for (int o = 16; o; o >>= 1)
        vmax = fmaxf(vmax, __shfl_xor_sync(0xffffffffu, vmax, o));

    float sum = 0.f;
#pragma unroll
    for (int k = 0; k < 16; k++) sum += __expf(x[k] - vmax);
#pragma unroll
    for (int o = 16; o; o >>= 1)
        sum += __shfl_xor_sync(0xffffffffu, sum, o);

    const float lse = vmax + logf(sum);

    float* orow = out + (size_t)row * E_;
#pragma unroll
    for (int q = 0; q < 4; q++) {
        float4 o4 = make_float4(x[4 * q] - lse, x[4 * q + 1] - lse,
                                x[4 * q + 2] - lse, x[4 * q + 3] - lse);
        ((float4*)orow)[q * 32 + lane] = o4;
    }
}

// ---------------------------------------------------------------------------
extern "C" void kernel_launch(void* const* d_in, const int* in_sizes, int n_in,
                              void* d_out, int out_size) {
    const float* decoder = (const float*)d_in[0];
    const float* encoder = (const float*)d_in[1];
    const int*   mask    = (const int*)d_in[2];
    const float* W1      = (const float*)d_in[3];
    const float* W2      = (const float*)d_in[4];
    const float* v       = (const float*)d_in[5];
    float* out           = (float*)d_out;

    cudaFuncSetAttribute(scores_kernel,
                         cudaFuncAttributeMaxDynamicSharedMemorySize, SCORES_SMEM);

    gemm_wmma_kernel<<<dim3(8, 12, B_), 128>>>(encoder, decoder, W1, W2);
    scores_kernel<<<dim3(E_ / 64, D_ / 32, B_), 256, SCORES_SMEM>>>(v);
    softmax_kernel<<<B_ * D_ / 8, 256>>>(mask, out);
}

// round 17
// speedup vs baseline: 1.8021x; 1.0054x over previous
#include <cuda_runtime.h>
#include <cuda_fp16.h>
#include <cuda_bf16.h>
#include <mma.h>
#include <cstddef>
#include <cstdint>

using namespace nvcuda;

#define B_   4
#define D_   256
#define E_   512
#define C_   256
#define NEG_INF -1e9f

typedef unsigned long long ull;

// GEMM inputs pre-converted to bf16 hi/lo (row-major [r][256])
__device__ __nv_bfloat16 g_enc_bh[B_ * E_ * C_], g_enc_bl[B_ * E_ * C_];
__device__ __nv_bfloat16 g_dec_bh[B_ * D_ * C_], g_dec_bl[B_ * D_ * C_];
__device__ __nv_bfloat16 g_w1h[C_ * C_], g_w1l[C_ * C_];
__device__ __nv_bfloat16 g_w2h[C_ * C_], g_w2l[C_ * C_];

// Projection buffers for scores: h = proj as half (c%8 0..3, 128/row);
// f = tanh(proj) f32 (c%8 4..7, 128/row).
__device__ __half g_enc_h[B_ * E_ * 128];
__device__ float  g_enc_f[B_ * E_ * 128];
__device__ __half g_dec_h[B_ * D_ * 128];
__device__ float  g_dec_f[B_ * D_ * 128];
__device__ float  g_scores[B_ * D_ * E_];

__device__ __forceinline__ __half2 tanh2h(__half2 x) {
    unsigned int r, xi = *reinterpret_cast<unsigned int*>(&x);
    asm("tanh.approx.f16x2 %0, %1;" : "=r"(r) : "r"(xi));
    return *reinterpret_cast<__half2*>(&r);
}
__device__ __forceinline__ __half2 u2h(unsigned int u) {
    return *reinterpret_cast<__half2*>(&u);
}
__device__ __forceinline__ float tanhf_fast(float x) {
    float y; asm("tanh.approx.f32 %0, %1;" : "=f"(y) : "f"(x)); return y;
}
__device__ __forceinline__ ull fma2_(ull a, ull b, ull c) {
    ull d; asm("fma.rn.f32x2 %0, %1, %2, %3;" : "=l"(d) : "l"(a), "l"(b), "l"(c)); return d;
}
__device__ __forceinline__ ull add2_(ull a, ull b) {
    ull d; asm("add.rn.f32x2 %0, %1, %2;" : "=l"(d) : "l"(a), "l"(b)); return d;
}
__device__ __forceinline__ ull mul2_(ull a, ull b) {
    ull d; asm("mul.rn.f32x2 %0, %1, %2;" : "=l"(d) : "l"(a), "l"(b)); return d;
}

#define ONE2_  0x3F8000003F800000ull
#define NTWO2_ 0xC0000000C0000000ull

__device__ __forceinline__ ull tanh_sum_acc1(ull ta, ull tb, ull nv, ull acc) {
    ull num = add2_(ta, tb);
    ull den = fma2_(ta, tb, ONE2_);
    ull r0;
    asm("{\n\t.reg .b32 lo, hi;\n\t"
        "mov.b64 {lo, hi}, %1;\n\t"
        "sub.u32 lo, 0x7EF311C3, lo;\n\t"
        "sub.u32 hi, 0x7EF311C3, hi;\n\t"
        "mov.b64 %0, {lo, hi};\n\t}" : "=l"(r0) : "l"(den));
    ull u1  = fma2_(den, r0, NTWO2_);
    ull r1n = mul2_(r0, u1);
    ull t   = mul2_(num, r1n);
    return fma2_(t, nv, acc);
}
__device__ __forceinline__ ull pku(unsigned lo, unsigned hi) {
    return ((ull)hi << 32) | lo;
}

// ---------------------------------------------------------------------------
// Convert: fp32 -> bf16 hi/lo for enc, dec, W1, W2 (one float4 per thread).
// ---------------------------------------------------------------------------
__global__ __launch_bounds__(256) void convert_kernel(
        const float* __restrict__ enc, const float* __restrict__ dec,
        const float* __restrict__ W1,  const float* __restrict__ W2) {
    int idx = blockIdx.x * 256 + threadIdx.x;
    const float* src;
    __nv_bfloat16 *dh, *dl;
    int base;
    if (idx < 131072)      { src = enc; dh = g_enc_bh; dl = g_enc_bl; base = idx; }
    else if (idx < 196608) { src = dec; dh = g_dec_bh; dl = g_dec_bl; base = idx - 131072; }
    else if (idx < 212992) { src = W1;  dh = g_w1h;    dl = g_w1l;    base = idx - 196608; }
    else                   { src = W2;  dh = g_w2h;    dl = g_w2l;    base = idx - 212992; }
    float4 x = ((const float4*)src)[base];
    float fx[4] = {x.x, x.y, x.z, x.w};
    unsigned short hb[4], lb[4];
#pragma unroll
    for (int j = 0; j < 4; j++) {
        __nv_bfloat16 h = __float2bfloat16(fx[j]);
        hb[j] = *reinterpret_cast<unsigned short*>(&h);
        __nv_bfloat16 l = __float2bfloat16(fx[j] - __bfloat162float(h));
        lb[j] = *reinterpret_cast<unsigned short*>(&l);
    }
    ((uint2*)dh)[base] = make_uint2((uint32_t)hb[0] | ((uint32_t)hb[1] << 16),
                                    (uint32_t)hb[2] | ((uint32_t)hb[3] << 16));
    ((uint2*)dl)[base] = make_uint2((uint32_t)lb[0] | ((uint32_t)lb[1] << 16),
                                    (uint32_t)lb[2] | ((uint32_t)lb[3] << 16));
}

// ---------------------------------------------------------------------------
// wmma GEMM v2: 64 rows x 64 cols per CTA, BK=64, 256 thr (8 warps, 4m x 2n).
// Inputs pre-converted bf16; fill = plain uint4 copies. Dynamic smem 36.9KB;
// Cs (17.4KB) aliases the stage buffers after the k-loop.
// D = Ah*Bh + Ah*Bl + Al*Bh (f32 accum).
// grid: (4 col tiles, 48 row tiles [0..31 enc, 32..47 dec]).
// ---------------------------------------------------------------------------
#define PW 72                          // bf16 stage pitch
#define SXH 0
#define SXL (64 * PW * 2)              // 9216
#define SWH (2 * 64 * PW * 2)          // 18432
#define SWL (3 * 64 * PW * 2)          // 27648
#define GEMM_SMEM (4 * 64 * PW * 2)    // 36864 B

__global__ __launch_bounds__(256) void gemm_wmma_kernel() {
    extern __shared__ char smc[];
    __nv_bfloat16* XH = (__nv_bfloat16*)(smc + SXH);
    __nv_bfloat16* XL = (__nv_bfloat16*)(smc + SXL);
    __nv_bfloat16* WH = (__nv_bfloat16*)(smc + SWH);
    __nv_bfloat16* WL = (__nv_bfloat16*)(smc + SWL);

    const int t = threadIdx.x;
    const int w = t >> 5;
    const int col0 = blockIdx.x * 64;
    const int yt = blockIdx.y;
    const bool is_enc = (yt < 32);
    const int b    = is_enc ? (yt >> 3) : ((yt - 32) >> 2);
    const int row0 = is_enc ? (yt & 7) * 64 : ((yt - 32) & 3) * 64;
    const int R    = is_enc ? E_ : D_;
    const __nv_bfloat16* Xh = (is_enc ? g_enc_bh : g_dec_bh) + ((size_t)b * R + row0) * C_;
    const __nv_bfloat16* Xl = (is_enc ? g_enc_bl : g_dec_bl) + ((size_t)b * R + row0) * C_;
    const __nv_bfloat16* Wh = (is_enc ? g_w1h : g_w2h) + (size_t)col0 * C_;
    const __nv_bfloat16* Wl = (is_enc ? g_w1l : g_w2l) + (size_t)col0 * C_;
    __half* outh = is_enc ? g_enc_h : g_dec_h;
    float*  outf = is_enc ? g_enc_f : g_dec_f;

    const int mw = (w >> 1) * 16;      // warp row base
    const int nw = (w & 1) * 32;       // warp col base

    wmma::fragment<wmma::matrix_a, 16, 16, 16, __nv_bfloat16, wmma::row_major> ah, al;
    wmma::fragment<wmma::matrix_b, 16, 16, 16, __nv_bfloat16, wmma::col_major> bh0, bh1, bl0, bl1;
    wmma::fragment<wmma::accumulator, 16, 16, 16, float> c0, c1;
    wmma::fill_fragment(c0, 0.f);
    wmma::fill_fragment(c1, 0.f);

    for (int k0 = 0; k0 < C_; k0 += 64) {
        __syncthreads();
        // Fill 4 stage tiles: 64 rows x 64 k each = 512 uint4 per tile
        for (int i = t; i < 512; i += 256) {
            int r = i >> 3, q = i & 7;
            *(uint4*)(XH + r * PW + q * 8) = ((const uint4*)(Xh + r * C_ + k0))[q];
            *(uint4*)(XL + r * PW + q * 8) = ((const uint4*)(Xl + r * C_ + k0))[q];
            *(uint4*)(WH + r * PW + q * 8) = ((const uint4*)(Wh + r * C_ + k0))[q];
            *(uint4*)(WL + r * PW + q * 8) = ((const uint4*)(Wl + r * C_ + k0))[q];
        }
        __syncthreads();

#pragma unroll
        for (int kk = 0; kk < 64; kk += 16) {
            wmma::load_matrix_sync(ah, XH + mw * PW + kk, PW);
            wmma::load_matrix_sync(al, XL + mw * PW + kk, PW);
            wmma::load_matrix_sync(bh0, WH + nw * PW + kk, PW);
            wmma::load_matrix_sync(bh1, WH + (nw + 16) * PW + kk, PW);
            wmma::load_matrix_sync(bl0, WL + nw * PW + kk, PW);
            wmma::load_matrix_sync(bl1, WL + (nw + 16) * PW + kk, PW);
            wmma::mma_sync(c0, ah, bh0, c0);
            wmma::mma_sync(c0, ah, bl0, c0);
            wmma::mma_sync(c0, al, bh0, c0);
            wmma::mma_sync(c1, ah, bh1, c1);
            wmma::mma_sync(c1, ah, bl1, c1);
            wmma::mma_sync(c1, al, bh1, c1);
        }
    }
    __syncthreads();                    // frags resident; free stage smem

    float* Cs = (float*)smc;            // [64][68] = 17408 B, aliases stages
    wmma::store_matrix_sync(Cs + mw * 68 + nw,      c0, 68, wmma::mem_row_major);
    wmma::store_matrix_sync(Cs + mw * 68 + nw + 16, c1, 68, wmma::mem_row_major);
    __syncthreads();

    // Epilogue: thread -> row = t>>2, seg = t&3 (16 cols, 2 c-groups)
    {
        const int row = t >> 2, seg = t & 3;
        const float* cr = Cs + row * 68 + seg * 16;
        const size_t r = (size_t)b * R + row0 + row;
        const int Gb = (col0 >> 3) + seg * 2;
#pragma unroll
        for (int gi = 0; gi < 2; gi++) {
            __half2 h0 = __floats2half2_rn(cr[8 * gi + 0], cr[8 * gi + 1]);
            __half2 h1 = __floats2half2_rn(cr[8 * gi + 2], cr[8 * gi + 3]);
            uint2 pk = make_uint2(*reinterpret_cast<unsigned int*>(&h0),
                                  *reinterpret_cast<unsigned int*>(&h1));
            *(uint2*)(outh + r * 128 + 4 * (Gb + gi)) = pk;
            float4 tq = make_float4(tanhf_fast(cr[8 * gi + 4]),
                                    tanhf_fast(cr[8 * gi + 5]),
                                    tanhf_fast(cr[8 * gi + 6]),
                                    tanhf_fast(cr[8 * gi + 7]));
            *(float4*)(outf + r * 128 + 4 * (Gb + gi)) = tq;
        }
    }
}

// ---------------------------------------------------------------------------
// Scores, warp-specialized 4+4 (R12, proven).
// ---------------------------------------------------------------------------
#define EPH_O 0
#define DPH_O (EPH_O + 64 * 66)
#define EPF_O (DPH_O + 32 * 66)
#define DPF_O (EPF_O + 64 * 132)
#define VH_O  (DPF_O + 32 * 132)
#define VFN_O (VH_O + 64)
#define PS_O  (VFN_O + 128)
#define SCORES_SMEM ((PS_O + 2048) * 4)

__global__ __launch_bounds__(256, 2) void scores_kernel(const float* __restrict__ v_g) {
    extern __shared__ unsigned int smu[];
    unsigned int* eph = smu + EPH_O;
    unsigned int* dph = smu + DPH_O;
    float*        epf = (float*)(smu + EPF_O);
    float*        dpf = (float*)(smu + DPF_O);
    unsigned int* vh  = smu + VH_O;
    float*        vfn = (float*)(smu + VFN_O);
    float*        ps  = (float*)(smu + PS_O);

    const int b  = blockIdx.z;
    const int d0 = blockIdx.y * 32;
    const int e0 = blockIdx.x * 64;
    const int t  = threadIdx.x;

    const __half* ehsrc = g_enc_h + ((size_t)b * E_ + e0) * 128;
    for (int i = t; i < 64 * 32; i += 256) {
        int r = i >> 5, q = i & 31;
        uint2 s = ((const uint2*)ehsrc)[r * 32 + q];
        *(uint2*)(eph + r * 66 + q * 2) = s;
    }
    const __half* dhsrc = g_dec_h + ((size_t)b * D_ + d0) * 128;
    for (int i = t; i < 32 * 32; i += 256) {
        int r = i >> 5, q = i & 31;
        uint2 s = ((const uint2*)dhsrc)[r * 32 + q];
        *(uint2*)(dph + r * 66 + q * 2) = s;
    }
    const float* efsrc = g_enc_f + ((size_t)b * E_ + e0) * 128;
    for (int i = t; i < 64 * 32; i += 256) {
        int r = i >> 5, q = i & 31;
        uint4 s = ((const uint4*)efsrc)[r * 32 + q];
        *(uint4*)(epf + r * 132 + q * 4) = s;
    }
    const float* dfsrc = g_dec_f + ((size_t)b * D_ + d0) * 128;
    for (int i = t; i < 32 * 32; i += 256) {
        int r = i >> 5, q = i & 31;
        uint4 s = ((const uint4*)dfsrc)[r * 32 + q];
        *(uint4*)(dpf + r * 132 + q * 4) = s;
    }
    if (t < 64) {
        int g = t >> 1, h = t & 1;
        __half2 p = __floats2half2_rn(v_g[8 * g + 2 * h], v_g[8 * g + 2 * h + 1]);
        vh[t] = *reinterpret_cast<unsigned int*>(&p);
    }
    if (t < 128) {
        vfn[t] = -v_g[8 * (t >> 2) + 4 + (t & 3)];
    }
    __syncthreads();

    const int w  = t >> 5;
    const int el = t & 31;

    if (w < 4) {
        const unsigned int* eh0 = eph + el * 66;
        const unsigned int* eh1 = eph + (el + 32) * 66;
        const unsigned int* dhb = dph + (8 * w) * 66;

        __half2 ah[16];
        float facc[16];
#pragma unroll
        for (int p = 0; p < 16; p++) {
            ah[p] = __floats2half2_rn(0.f, 0.f);
            facc[p] = 0.f;
        }
        for (int g = 0; g < 32; g++) {
            uint2 vv = *(const uint2*)(vh + 2 * g);
            __half2 v0 = u2h(vv.x), v1 = u2h(vv.y);
            uint2 ea = *(const uint2*)(eh0 + 2 * g);
            uint2 eb = *(const uint2*)(eh1 + 2 * g);
            __half2 ea0 = u2h(ea.x), ea1 = u2h(ea.y);
            __half2 eb0 = u2h(eb.x), eb1 = u2h(eb.y);
#pragma unroll
            for (int i = 0; i < 8; i++) {
                uint2 dhp = *(const uint2*)(dhb + i * 66 + 2 * g);
                __half2 dh0 = u2h(dhp.x), dh1 = u2h(dhp.y);
                __half2 s0 = ah[i * 2];
                s0 = __hfma2(tanh2h(__hadd2(dh0, ea0)), v0, s0);
                s0 = __hfma2(tanh2h(__hadd2(dh1, ea1)), v1, s0);
                ah[i * 2] = s0;
                __half2 s1 = ah[i * 2 + 1];
                s1 = __hfma2(tanh2h(__hadd2(dh0, eb0)), v0, s1);
                s1 = __hfma2(tanh2h(__hadd2(dh1, eb1)), v1, s1);
                ah[i * 2 + 1] = s1;
            }
            if ((g & 3) == 3) {
#pragma unroll
                for (int p = 0; p < 16; p++) {
                    float2 f = __half22float2(ah[p]);
                    facc[p] += f.x + f.y;
                    ah[p] = __floats2half2_rn(0.f, 0.f);
                }
            }
        }
#pragma unroll
        for (int i = 0; i < 8; i++) {
            ps[(8 * w + i) * 64 + el]      = facc[i * 2];
            ps[(8 * w + i) * 64 + el + 32] = facc[i * 2 + 1];
        }
    } else {
        const int w4 = w - 4;
        const float* ef0 = epf + el * 132;
        const float* ef1 = epf + (el + 32) * 132;
        const float* dfb = dpf + (8 * w4) * 132;

        ull af[16];
#pragma unroll
        for (int p = 0; p < 16; p++) af[p] = 0ull;

        for (int g = 0; g < 32; g++) {
            uint4 nvq = *(const uint4*)(vfn + 4 * g);
            ull nv0 = pku(nvq.x, nvq.y);
            ull nv1 = pku(nvq.z, nvq.w);
            uint4 e0q = *(const uint4*)(ef0 + 4 * g);
            uint4 e1q = *(const uint4*)(ef1 + 4 * g);
            ull e0a = pku(e0q.x, e0q.y), e0b = pku(e0q.z, e0q.w);
            ull e1a = pku(e1q.x, e1q.y), e1b = pku(e1q.z, e1q.w);
#pragma unroll
            for (int i = 0; i < 8; i++) {
                uint4 dq = *(const uint4*)(dfb + i * 132 + 4 * g);
                ull da = pku(dq.x, dq.y), db = pku(dq.z, dq.w);
                ull a0 = af[i * 2];
                a0 = tanh_sum_acc1(da, e0a, nv0, a0);
                a0 = tanh_sum_acc1(db, e0b, nv1, a0);
                af[i * 2] = a0;
                ull a1 = af[i * 2 + 1];
                a1 = tanh_sum_acc1(da, e1a, nv0, a1);
                a1 = tanh_sum_acc1(db, e1b, nv1, a1);
                af[i * 2 + 1] = a1;
            }
        }
        __syncthreads();
#pragma unroll
        for (int i = 0; i < 8; i++) {
            float lo0, hi0, lo1, hi1;
            asm("mov.b64 {%0, %1}, %2;" : "=f"(lo0), "=f"(hi0) : "l"(af[i * 2]));
            asm("mov.b64 {%0, %1}, %2;" : "=f"(lo1), "=f"(hi1) : "l"(af[i * 2 + 1]));
            float m0 = ps[(8 * w4 + i) * 64 + el];
            float m1 = ps[(8 * w4 + i) * 64 + el + 32];
            float* srow = g_scores + ((size_t)b * D_ + d0 + 8 * w4 + i) * E_ + e0 + el;
            srow[0]  = m0 + lo0 + hi0;
            srow[32] = m1 + lo1 + hi1;
        }
        return;
    }
    __syncthreads();
}

// ---------------------------------------------------------------------------
// Masked log-softmax, one warp per row.
// ---------------------------------------------------------------------------
__global__ __launch_bounds__(256) void softmax_kernel(const int* __restrict__ mask,
                                                      float* __restrict__ out) {
    const int row  = blockIdx.x * 8 + (threadIdx.x >> 5);
    const int lane = threadIdx.x & 31;

    const float4* s = (const float4*)(g_scores + (size_t)row * E_);
    const int4*   m = (const int4*)(mask + (size_t)row * E_);

    float x[16];
    float vmax = -3.0e38f;
#pragma unroll
    for (int q = 0; q < 4; q++) {
        float4 sv = s[q * 32 + lane];
        int4   mv = m[q * 32 + lane];
        x[4 * q + 0] = mv.x ? sv.x : NEG_INF;
        x[4 * q + 1] = mv.y ? sv.y : NEG_INF;
        x[4 * q + 2] = mv.z ? sv.z : NEG_INF;
        x[4 * q + 3] = mv.w ? sv.w : NEG_INF;
        vmax = fmaxf(vmax, fmaxf(fmaxf(x[4 * q], x[4 * q + 1]),
                                 fmaxf(x[4 * q + 2], x[4 * q + 3])));
    }
#pragma unroll
    for (int o = 16; o; o >>= 1)
        vmax = fmaxf(vmax, __shfl_xor_sync(0xffffffffu, vmax, o));

    float sum = 0.f;
#pragma unroll
    for (int k = 0; k < 16; k++) sum += __expf(x[k] - vmax);
#pragma unroll
    for (int o = 16; o; o >>= 1)
        sum += __shfl_xor_sync(0xffffffffu, sum, o);

    const float lse = vmax + logf(sum);

    float* orow = out + (size_t)row * E_;
#pragma unroll
    for (int q = 0; q < 4; q++) {
        float4 o4 = make_float4(x[4 * q] - lse, x[4 * q + 1] - lse,
                                x[4 * q + 2] - lse, x[4 * q + 3] - lse);
        ((float4*)orow)[q * 32 + lane] = o4;
    }
}

// ---------------------------------------------------------------------------
extern "C" void kernel_launch(void* const* d_in, const int* in_sizes, int n_in,
                              void* d_out, int out_size) {
    const float* decoder = (const float*)d_in[0];
    const float* encoder = (const float*)d_in[1];
    const int*   mask    = (const int*)d_in[2];
    const float* W1      = (const float*)d_in[3];
    const float* W2      = (const float*)d_in[4];
    const float* v       = (const float*)d_in[5];
    float* out           = (float*)d_out;

    cudaFuncSetAttribute(gemm_wmma_kernel,
                         cudaFuncAttributeMaxDynamicSharedMemorySize, GEMM_SMEM);
    cudaFuncSetAttribute(scores_kernel,
                         cudaFuncAttributeMaxDynamicSharedMemorySize, SCORES_SMEM);

    convert_kernel<<<896, 256>>>(encoder, decoder, W1, W2);
    gemm_wmma_kernel<<<dim3(4, 48), 256, GEMM_SMEM>>>();
    scores_kernel<<<dim3(E_ / 64, D_ / 32, B_), 256, SCORES_SMEM>>>(v);
    softmax_kernel<<<B_ * D_ / 8, 256>>>(mask, out);
}